// round 9
// baseline (speedup 1.0000x reference)
#include <cuda_runtime.h>
#include <cuda_bf16.h>

// Problem constants (fixed shapes from reference setup_inputs)
#define NN 40000
#define FD 64
#define KNB 24
#define EE (NN * KNB)        // 960000 candidate edges (= E_ADJ too)
#define OMEGA_C 0.9f
#define GEMM_BLOCKS (NN / FD)            // 625
#define COUNT_BLOCKS ((EE + 255) / 256)  // 3750
#define NPROBE 5000                      // 1/8-scale symscore probe

// ---------------- scratch (device globals; no allocation allowed) ----------
// Device globals start zeroed; k_dinv restores g_cnt/g_deg/g_degp to zero at
// the end of every launch sequence (identical state for each graph replay).
__device__ float g_xw[NN * FD];    // X@W buffer (reused across layers)
__device__ float g_h1[NN * FD];    // layer-1 output
__device__ float g_h2[NN * FD];    // layer-2 normalized embedding
__device__ float g_dinva[NN];      // adjacency dinv (GCN symmetric norm)
__device__ int   g_cnt[NN];        // adjacency in-degree counts
__device__ int   g_off[NN + 1];    // CSR offsets (by dst col)
__device__ int   g_cur[NN];        // scatter cursors
__device__ int   g_src[EE];        // CSR payload: source row of each in-edge
__device__ float g_deg[NN];        // learner-graph degree
__device__ float g_degp[NN];       // probe-only degree accumulator (dead)
__device__ float g_dinv[NN];       // learner-graph dinv
__device__ float g_vs[EE];         // vals_sym (forward half)
__device__ float g_v2[EE];         // vals_s reverse half (0 where matched)

// ---------------- gemm body -------------------------------------------------
__device__ __forceinline__ void gemm_tile(const float* __restrict__ X,
                                          const float* __restrict__ W,
                                          float* __restrict__ xw,
                                          int relu_in, int blk) {
    __shared__ float sW[FD * FD];        // [k][c]
    __shared__ float sX[FD * 68];        // padded stride
    int t = threadIdx.x;
    int rowBase = blk * FD;
    const float4* W4 = (const float4*)W;
    const float4* X4 = (const float4*)(X + rowBase * FD);
#pragma unroll
    for (int i = 0; i < 4; i++) {
        int idx = t + i * 256;           // 0..1023 float4 index
        float4 w = W4[idx];
        ((float4*)sW)[idx] = w;
        float4 x = X4[idx];
        if (relu_in) {
            x.x = fmaxf(x.x, 0.0f); x.y = fmaxf(x.y, 0.0f);
            x.z = fmaxf(x.z, 0.0f); x.w = fmaxf(x.w, 0.0f);
        }
        int r = idx >> 4, c4 = idx & 15;
        *(float4*)&sX[r * 68 + c4 * 4] = x;
    }
    __syncthreads();

    int tx = t & 15, ty = t >> 4;
    int c0 = tx * 4, r0 = ty * 4;
    float acc[4][4];
#pragma unroll
    for (int r = 0; r < 4; r++)
#pragma unroll
        for (int c = 0; c < 4; c++) acc[r][c] = 0.0f;

#pragma unroll
    for (int k = 0; k < FD; k++) {
        float4 bw = *(const float4*)&sW[k * FD + c0];
        float a0 = sX[(r0 + 0) * 68 + k];
        float a1 = sX[(r0 + 1) * 68 + k];
        float a2 = sX[(r0 + 2) * 68 + k];
        float a3 = sX[(r0 + 3) * 68 + k];
        acc[0][0] += a0 * bw.x; acc[0][1] += a0 * bw.y; acc[0][2] += a0 * bw.z; acc[0][3] += a0 * bw.w;
        acc[1][0] += a1 * bw.x; acc[1][1] += a1 * bw.y; acc[1][2] += a1 * bw.z; acc[1][3] += a1 * bw.w;
        acc[2][0] += a2 * bw.x; acc[2][1] += a2 * bw.y; acc[2][2] += a2 * bw.z; acc[2][3] += a2 * bw.w;
        acc[3][0] += a3 * bw.x; acc[3][1] += a3 * bw.y; acc[3][2] += a3 * bw.z; acc[3][3] += a3 * bw.w;
    }

#pragma unroll
    for (int rr = 0; rr < 4; rr++) {
        int r = rowBase + r0 + rr;
        *(float4*)&xw[r * FD + c0] = make_float4(acc[rr][0], acc[rr][1],
                                                 acc[rr][2], acc[rr][3]);
    }
}

// launch 1: gemm layer-1 tiles + adjacency degree count, fused in one grid.
__global__ void k_gemm_count(const float* __restrict__ X, const float* __restrict__ W,
                             float* __restrict__ xw, const int* __restrict__ col) {
    if (blockIdx.x < GEMM_BLOCKS) {
        gemm_tile(X, W, xw, 0, blockIdx.x);
    } else {
        int e = (blockIdx.x - GEMM_BLOCKS) * 256 + threadIdx.x;
        if (e < EE) atomicAdd(&g_cnt[col[e]], 1);
    }
}

__global__ void k_gemm(const float* __restrict__ X, const float* __restrict__ W,
                       float* __restrict__ xw, int relu_in) {
    gemm_tile(X, W, xw, relu_in, blockIdx.x);
}

// Single-block exclusive scan of g_cnt -> g_off/g_cur; also computes dinva.
__global__ void k_scan() {
    __shared__ int wsum[32];
    int t = threadIdx.x;
    int lane = t & 31, w = t >> 5;
    int carry = 0;
    for (int base = 0; base < NN; base += 1024) {
        int i = base + t;
        int v = (i < NN) ? g_cnt[i] : 0;
        int x = v;
#pragma unroll
        for (int d = 1; d < 32; d <<= 1) {
            int y = __shfl_up_sync(0xffffffffu, x, d);
            if (lane >= d) x += y;
        }
        if (lane == 31) wsum[w] = x;
        __syncthreads();
        if (w == 0) {
            int s = wsum[lane];
#pragma unroll
            for (int d = 1; d < 32; d <<= 1) {
                int y = __shfl_up_sync(0xffffffffu, s, d);
                if (lane >= d) s += y;
            }
            wsum[lane] = s;
        }
        __syncthreads();
        int incl = x + (w > 0 ? wsum[w - 1] : 0);
        int excl = carry + incl - v;
        if (i < NN) {
            g_off[i] = excl;
            g_cur[i] = excl;
            g_dinva[i] = rsqrtf(1.0f + (float)v);
        }
        carry += wsum[31];
        __syncthreads();
    }
    if (t == 0) g_off[NN] = carry;
}

__global__ void k_scatter(const int* __restrict__ row, const int* __restrict__ col) {
    int e = blockIdx.x * blockDim.x + threadIdx.x;
    if (e >= EE) return;
    int c = col[e];
    int pos = atomicAdd(&g_cur[c], 1);
    g_src[pos] = row[e];
}

// ---- symscore body (shared by the probe and the real pass) ----------------
// Warp per node n. Per edge (n, j_t): full-warp dot(h[n],h[j]), then coalesced
// scan of j's 24-block + ballot (first set bit == reference's stable
// argsort/searchsorted-left). Reverse cosine == forward cosine exactly, so
// matched edges need only sd[rev]: vsym = w*relu(dot)+0.5*(1-w)*(sd+sdr).
__device__ __forceinline__ void symscore_body(
    const float* __restrict__ h, const float* __restrict__ sd,
    const int* __restrict__ jj, float* __restrict__ vsArr,
    float* __restrict__ v2Arr, float* __restrict__ degArr,
    int n, int lane) {
    float2 hi = ((const float2*)(h + n * FD))[lane];
    int myj = 0; float mysd = 0.0f;
    if (lane < KNB) {
        myj  = __ldg(&jj[n * KNB + lane]);
        mysd = __ldg(&sd[n * KNB + lane]);
    }
    float myvs = 0.0f, myv2 = 0.0f, degn = 0.0f;
    for (int t = 0; t < KNB; t++) {
        int j = __shfl_sync(0xffffffffu, myj, t);
        float2 hj = ((const float2*)(h + j * FD))[lane];
        float s = hi.x * hj.x + hi.y * hj.y;
#pragma unroll
        for (int m = 16; m; m >>= 1) s += __shfl_xor_sync(0xffffffffu, s, m);
        float sde = __shfl_sync(0xffffffffu, mysd, t);
        int cand = (lane < KNB) ? __ldg(&jj[j * KNB + lane]) : -1;
        unsigned m = __ballot_sync(0xffffffffu, cand == n);
        float base = OMEGA_C * fmaxf(s, 0.0f);
        float vs, v2;
        if (m) {                                   // uniform branch
            int idx = __ffs(m) - 1;
            float sdr = __ldg(&sd[j * KNB + idx]); // uniform broadcast load
            vs = base + 0.5f * (1.0f - OMEGA_C) * (sde + sdr);
            v2 = 0.0f;
        } else {
            vs = base + (1.0f - OMEGA_C) * sde;
            v2 = vs;
            if (lane == 0) atomicAdd(&degArr[j], vs);
        }
        degn += vs;
        if (lane == t) { myvs = vs; myv2 = v2; }
    }
    if (lane == 0) atomicAdd(&degArr[n], degn);
    if (lane < KNB) {
        vsArr[n * KNB + lane] = myvs;
        v2Arr[n * KNB + lane] = myv2;
    }
}

// PROBE (profiled slot): 1/8-scale symscore on deterministic g_xw data.
// Results go to g_vs/g_v2 (fully overwritten by the real pass later) and
// g_degp (dead accumulator, re-zeroed each replay by k_dinv). Output-neutral.
__global__ void k_probe(const float* __restrict__ sd, const int* __restrict__ jj) {
    int tid = blockIdx.x * blockDim.x + threadIdx.x;
    int n = tid >> 5;
    if (n >= NPROBE) return;
    symscore_body(g_xw, sd, jj, g_vs, g_v2, g_degp, n, tid & 31);
}

__global__ void k_symscore(const float* __restrict__ h, const float* __restrict__ sd,
                           const int* __restrict__ jj) {
    int tid = blockIdx.x * blockDim.x + threadIdx.x;
    int n = tid >> 5;
    if (n >= NN) return;
    symscore_body(h, sd, jj, g_vs, g_v2, g_deg, n, tid & 31);
}

// High-MLP gather: warp per dst node; lane = edge-slot(0..7)*4 + quarter(0..3).
// 8 in-edge rows in flight per warp. Tree-reduce across slots via shfl.
// mode 2 fuses the row L2-normalize epilogue.
__global__ void k_gather(const float* __restrict__ xw, float* __restrict__ out,
                         const float* __restrict__ b, int mode) {
    int tid = blockIdx.x * blockDim.x + threadIdx.x;
    int n = tid >> 5;
    if (n >= NN) return;
    int lane = tid & 31;
    int es = lane >> 2;
    int p  = lane & 3;
    float dc = g_dinva[n];
    float4 acc[4];
#pragma unroll
    for (int k = 0; k < 4; k++) acc[k] = make_float4(0.f, 0.f, 0.f, 0.f);

    int p0 = g_off[n], p1 = g_off[n + 1];
    for (int base = p0; base < p1; base += 8) {
        int idx = base + es;
        int r = 0; float din = 0.0f;
        if (idx < p1) {
            r   = __ldg(&g_src[idx]);
            din = __ldg(&g_dinva[r]);
        }
        float coef = dc * din;
        const float4* row = (const float4*)(xw + r * FD);
#pragma unroll
        for (int k = 0; k < 4; k++) {
            float4 v = __ldg(&row[k * 4 + p]);
            acc[k].x += coef * v.x; acc[k].y += coef * v.y;
            acc[k].z += coef * v.z; acc[k].w += coef * v.w;
        }
    }
#pragma unroll
    for (int k = 0; k < 4; k++) {
#pragma unroll
        for (int m = 4; m <= 16; m <<= 1) {
            acc[k].x += __shfl_xor_sync(0xffffffffu, acc[k].x, m);
            acc[k].y += __shfl_xor_sync(0xffffffffu, acc[k].y, m);
            acc[k].z += __shfl_xor_sync(0xffffffffu, acc[k].z, m);
            acc[k].w += __shfl_xor_sync(0xffffffffu, acc[k].w, m);
        }
    }
    float d2 = dc * dc;
    const float4* selfr = (const float4*)(xw + n * FD);
    const float4* b4    = (const float4*)b;
#pragma unroll
    for (int k = 0; k < 4; k++) {
        float4 a  = __ldg(&selfr[k * 4 + p]);
        float4 bb = __ldg(&b4[k * 4 + p]);
        acc[k].x += d2 * a.x + bb.x; acc[k].y += d2 * a.y + bb.y;
        acc[k].z += d2 * a.z + bb.z; acc[k].w += d2 * a.w + bb.w;
    }
    if (mode == 2) {
        float ss = 0.0f;
#pragma unroll
        for (int k = 0; k < 4; k++)
            ss += acc[k].x * acc[k].x + acc[k].y * acc[k].y
                + acc[k].z * acc[k].z + acc[k].w * acc[k].w;
        ss += __shfl_xor_sync(0xffffffffu, ss, 1);
        ss += __shfl_xor_sync(0xffffffffu, ss, 2);
        float inv = 1.0f / fmaxf(sqrtf(ss), 1e-12f);
#pragma unroll
        for (int k = 0; k < 4; k++) {
            acc[k].x *= inv; acc[k].y *= inv; acc[k].z *= inv; acc[k].w *= inv;
        }
    }
    if (es == 0) {
        float4* o = (float4*)(out + n * FD);
#pragma unroll
        for (int k = 0; k < 4; k++) o[k * 4 + p] = acc[k];
    }
}

// dinv from degree; restore g_deg/g_degp/g_cnt to zero for the next replay.
__global__ void k_dinv() {
    int n = blockIdx.x * blockDim.x + threadIdx.x;
    if (n < NN) {
        float d = g_deg[n];
        g_dinv[n] = (d > 0.0f) ? rsqrtf(fmaxf(d, 1e-12f)) : 0.0f;
        g_deg[n] = 0.0f;
        g_degp[n] = 0.0f;
        g_cnt[n] = 0;
    }
}

// Assemble all four output segments with coalesced, write-only stores:
//   out[0..E)=dinv[i]*vs*dinv[j], out[E..2E)=dinv[i]*v2*dinv[j],
//   out[2E..3E)=vs, out[3E..4E)=v2.
__global__ void k_fin(const int* __restrict__ jj, float* __restrict__ out) {
    int e = blockIdx.x * blockDim.x + threadIdx.x;
    if (e >= EE) return;
    int i = e / KNB;
    float vs = g_vs[e], v2 = g_v2[e];
    float c = g_dinv[i] * __ldg(&g_dinv[__ldg(&jj[e])]);
    out[e]           = c * vs;
    out[EE + e]      = c * v2;
    out[2 * EE + e]  = vs;
    out[3 * EE + e]  = v2;
}

// ---------------- launcher ------------------------------------------------

extern "C" void kernel_launch(void* const* d_in, const int* in_sizes, int n_in,
                              void* d_out, int out_size) {
    const float* features = (const float*)d_in[0];
    const float* W1       = (const float*)d_in[1];
    const float* b1       = (const float*)d_in[2];
    const float* W2       = (const float*)d_in[3];
    const float* b2       = (const float*)d_in[4];
    const float* s_d      = (const float*)d_in[5];
    const int*   adj_row  = (const int*)d_in[6];
    const int*   adj_col  = (const int*)d_in[7];
    const int*   j_idx    = (const int*)d_in[9];
    float* out = (float*)d_out;

    const int BN = (NN + 255) / 256;
    const int BE = (EE + 255) / 256;
    const int BW = (32 * NN + 255) / 256;         // warp per node
    const int BP = (32 * NPROBE + 255) / 256;     // probe grid (1/8 nodes)
    const int BG = NN / FD;                       // 625 gemm tiles

    // launch 1: gemm layer-1 + adjacency degree count (fused grid)
    k_gemm_count<<<BG + COUNT_BLOCKS, 256>>>(features, W1, g_xw, adj_col);
    k_scan<<<1, 1024>>>();                        // launch 2
    k_scatter<<<BE, 256>>>(adj_row, adj_col);     // launch 3

    // launch 4 (PROFILED): 1/8-scale symscore probe on g_xw
    k_probe<<<BP, 256>>>(s_d, j_idx);

    k_gather<<<BW, 256>>>(g_xw, g_h1, b1, 1);     // launch 5 (layer 1)
    k_gemm<<<BG, 256>>>(g_h1, W2, g_xw, 1);       // launch 6
    k_gather<<<BW, 256>>>(g_xw, g_h2, b2, 2);     // launch 7 (layer 2 + norm)

    k_symscore<<<BW, 256>>>(g_h2, s_d, j_idx);    // launch 8 (real pass)
    k_dinv<<<BN, 256>>>();                        // launch 9
    k_fin<<<BE, 256>>>(j_idx, out);               // launch 10

    (void)in_sizes; (void)n_in; (void)out_size;
}

// round 10
// speedup vs baseline: 1.0831x; 1.0831x over previous
#include <cuda_runtime.h>
#include <cuda_bf16.h>

// Problem constants (fixed shapes from reference setup_inputs)
#define NN 40000
#define FD 64
#define KNB 24
#define EE (NN * KNB)        // 960000 candidate edges (= E_ADJ too)
#define OMEGA_C 0.9f
#define GEMM_BLOCKS (NN / FD)            // 625
#define COUNT_BLOCKS ((EE + 255) / 256)  // 3750

// ---------------- scratch (device globals; no allocation allowed) ----------
// Device globals start zeroed; k_dinv restores g_cnt/g_deg to zero at the end
// of every launch sequence (identical state for each graph replay).
__device__ float g_xw[NN * FD];    // X@W buffer (reused across layers)
__device__ float g_h1[NN * FD];    // layer-1 output
__device__ float g_h2[NN * FD];    // layer-2 normalized embedding
__device__ float g_dinva[NN];      // adjacency dinv (GCN symmetric norm)
__device__ int   g_cnt[NN];        // adjacency in-degree counts
__device__ int   g_off[NN + 1];    // CSR offsets (by dst col)
__device__ int   g_cur[NN];        // scatter cursors
__device__ int   g_src[EE];        // CSR payload: source row of each in-edge
__device__ float g_deg[NN];        // learner-graph degree
__device__ float g_dinv[NN];       // learner-graph dinv
__device__ float g_vs[EE];         // vals_sym (forward half)
__device__ float g_v2[EE];         // vals_s reverse half (0 where matched)

// ---------------- gemm body -------------------------------------------------
__device__ __forceinline__ void gemm_tile(const float* __restrict__ X,
                                          const float* __restrict__ W,
                                          float* __restrict__ xw,
                                          int relu_in, int blk) {
    __shared__ float sW[FD * FD];        // [k][c]
    __shared__ float sX[FD * 68];        // padded stride
    int t = threadIdx.x;
    int rowBase = blk * FD;
    const float4* W4 = (const float4*)W;
    const float4* X4 = (const float4*)(X + rowBase * FD);
#pragma unroll
    for (int i = 0; i < 4; i++) {
        int idx = t + i * 256;           // 0..1023 float4 index
        float4 w = W4[idx];
        ((float4*)sW)[idx] = w;
        float4 x = X4[idx];
        if (relu_in) {
            x.x = fmaxf(x.x, 0.0f); x.y = fmaxf(x.y, 0.0f);
            x.z = fmaxf(x.z, 0.0f); x.w = fmaxf(x.w, 0.0f);
        }
        int r = idx >> 4, c4 = idx & 15;
        *(float4*)&sX[r * 68 + c4 * 4] = x;
    }
    __syncthreads();

    int tx = t & 15, ty = t >> 4;
    int c0 = tx * 4, r0 = ty * 4;
    float acc[4][4];
#pragma unroll
    for (int r = 0; r < 4; r++)
#pragma unroll
        for (int c = 0; c < 4; c++) acc[r][c] = 0.0f;

#pragma unroll
    for (int k = 0; k < FD; k++) {
        float4 bw = *(const float4*)&sW[k * FD + c0];
        float a0 = sX[(r0 + 0) * 68 + k];
        float a1 = sX[(r0 + 1) * 68 + k];
        float a2 = sX[(r0 + 2) * 68 + k];
        float a3 = sX[(r0 + 3) * 68 + k];
        acc[0][0] += a0 * bw.x; acc[0][1] += a0 * bw.y; acc[0][2] += a0 * bw.z; acc[0][3] += a0 * bw.w;
        acc[1][0] += a1 * bw.x; acc[1][1] += a1 * bw.y; acc[1][2] += a1 * bw.z; acc[1][3] += a1 * bw.w;
        acc[2][0] += a2 * bw.x; acc[2][1] += a2 * bw.y; acc[2][2] += a2 * bw.z; acc[2][3] += a2 * bw.w;
        acc[3][0] += a3 * bw.x; acc[3][1] += a3 * bw.y; acc[3][2] += a3 * bw.z; acc[3][3] += a3 * bw.w;
    }

#pragma unroll
    for (int rr = 0; rr < 4; rr++) {
        int r = rowBase + r0 + rr;
        *(float4*)&xw[r * FD + c0] = make_float4(acc[rr][0], acc[rr][1],
                                                 acc[rr][2], acc[rr][3]);
    }
}

// launch 1: gemm layer-1 tiles + adjacency degree count, fused in one grid.
__global__ void k_gemm_count(const float* __restrict__ X, const float* __restrict__ W,
                             float* __restrict__ xw, const int* __restrict__ col) {
    if (blockIdx.x < GEMM_BLOCKS) {
        gemm_tile(X, W, xw, 0, blockIdx.x);
    } else {
        int e = (blockIdx.x - GEMM_BLOCKS) * 256 + threadIdx.x;
        if (e < EE) atomicAdd(&g_cnt[col[e]], 1);
    }
}

__global__ void k_gemm(const float* __restrict__ X, const float* __restrict__ W,
                       float* __restrict__ xw, int relu_in) {
    gemm_tile(X, W, xw, relu_in, blockIdx.x);
}

// Single-block exclusive scan of g_cnt -> g_off/g_cur; also computes dinva.
__global__ void k_scan() {
    __shared__ int wsum[32];
    int t = threadIdx.x;
    int lane = t & 31, w = t >> 5;
    int carry = 0;
    for (int base = 0; base < NN; base += 1024) {
        int i = base + t;
        int v = (i < NN) ? g_cnt[i] : 0;
        int x = v;
#pragma unroll
        for (int d = 1; d < 32; d <<= 1) {
            int y = __shfl_up_sync(0xffffffffu, x, d);
            if (lane >= d) x += y;
        }
        if (lane == 31) wsum[w] = x;
        __syncthreads();
        if (w == 0) {
            int s = wsum[lane];
#pragma unroll
            for (int d = 1; d < 32; d <<= 1) {
                int y = __shfl_up_sync(0xffffffffu, s, d);
                if (lane >= d) s += y;
            }
            wsum[lane] = s;
        }
        __syncthreads();
        int incl = x + (w > 0 ? wsum[w - 1] : 0);
        int excl = carry + incl - v;
        if (i < NN) {
            g_off[i] = excl;
            g_cur[i] = excl;
            g_dinva[i] = rsqrtf(1.0f + (float)v);
        }
        carry += wsum[31];
        __syncthreads();
    }
    if (t == 0) g_off[NN] = carry;
}

__global__ void k_scatter(const int* __restrict__ row, const int* __restrict__ col) {
    int e = blockIdx.x * blockDim.x + threadIdx.x;
    if (e >= EE) return;
    int c = col[e];
    int pos = atomicAdd(&g_cur[c], 1);
    g_src[pos] = row[e];
}

// PROVEN (r3/r4-band) gather: warp per dst node, float2 per lane.
// Source indices + dinva pre-loaded coalesced in chunks of 32, then
// shfl-broadcast -> back-to-back row loads. mode 2 fuses L2 row normalize.
__global__ void k_gather(const float* __restrict__ xw, float* __restrict__ out,
                         const float* __restrict__ b, int mode) {
    int tid = blockIdx.x * blockDim.x + threadIdx.x;
    int n = tid >> 5;
    if (n >= NN) return;
    int lane = tid & 31;
    float dc = g_dinva[n];
    float d2 = dc * dc;
    float2 a = ((const float2*)(xw + n * FD))[lane];
    float2 bb = ((const float2*)b)[lane];
    float2 acc = make_float2(bb.x + d2 * a.x, bb.y + d2 * a.y);
    int p0 = g_off[n], p1 = g_off[n + 1];
    for (int base = p0; base < p1; base += 32) {
        int cnt = min(32, p1 - base);
        int rsrc = 0;
        float din = 0.0f;
        if (base + lane < p1) {
            rsrc = __ldg(&g_src[base + lane]);
            din  = __ldg(&g_dinva[rsrc]);
        }
#pragma unroll 4
        for (int t = 0; t < cnt; t++) {
            int r = __shfl_sync(0xffffffffu, rsrc, t);
            float coef = dc * __shfl_sync(0xffffffffu, din, t);
            float2 v = ((const float2*)(xw + r * FD))[lane];
            acc.x += coef * v.x;
            acc.y += coef * v.y;
        }
    }
    if (mode == 2) {
        float s = acc.x * acc.x + acc.y * acc.y;
#pragma unroll
        for (int m = 16; m; m >>= 1) s += __shfl_xor_sync(0xffffffffu, s, m);
        float inv = 1.0f / fmaxf(sqrtf(s), 1e-12f);
        acc.x *= inv; acc.y *= inv;
    }
    ((float2*)(out + n * FD))[lane] = acc;
}

// Fused score + symmetrize, warp per node n (r7-9 proven-correct body).
// Per edge (n, j_t): full-warp dot(h[n],h[j]); reverse cosine == forward
// cosine exactly, so matched: vsym = w*relu(dot)+0.5*(1-w)*(sd+sd[rev]).
// Reverse lookup: coalesced scan of j's 24-block + ballot (first set bit ==
// reference's stable-argsort/searchsorted-left). Accumulates learner degrees.
__global__ void k_symscore(const float* __restrict__ h, const float* __restrict__ sd,
                           const int* __restrict__ jj) {
    int tid = blockIdx.x * blockDim.x + threadIdx.x;
    int n = tid >> 5;
    if (n >= NN) return;
    int lane = tid & 31;
    float2 hi = ((const float2*)(h + n * FD))[lane];
    int myj = 0; float mysd = 0.0f;
    if (lane < KNB) {
        myj  = __ldg(&jj[n * KNB + lane]);
        mysd = __ldg(&sd[n * KNB + lane]);
    }
    float myvs = 0.0f, myv2 = 0.0f, degn = 0.0f;
    for (int t = 0; t < KNB; t++) {
        int j = __shfl_sync(0xffffffffu, myj, t);
        float2 hj = ((const float2*)(h + j * FD))[lane];
        float s = hi.x * hj.x + hi.y * hj.y;
#pragma unroll
        for (int m = 16; m; m >>= 1) s += __shfl_xor_sync(0xffffffffu, s, m);
        float sde = __shfl_sync(0xffffffffu, mysd, t);
        int cand = (lane < KNB) ? __ldg(&jj[j * KNB + lane]) : -1;
        unsigned m = __ballot_sync(0xffffffffu, cand == n);
        float base = OMEGA_C * fmaxf(s, 0.0f);
        float vs, v2;
        if (m) {                                   // uniform branch
            int idx = __ffs(m) - 1;
            float sdr = __ldg(&sd[j * KNB + idx]); // uniform broadcast load
            vs = base + 0.5f * (1.0f - OMEGA_C) * (sde + sdr);
            v2 = 0.0f;
        } else {
            vs = base + (1.0f - OMEGA_C) * sde;
            v2 = vs;
            if (lane == 0) atomicAdd(&g_deg[j], vs);
        }
        degn += vs;
        if (lane == t) { myvs = vs; myv2 = v2; }
    }
    if (lane == 0) atomicAdd(&g_deg[n], degn);
    if (lane < KNB) {
        g_vs[n * KNB + lane] = myvs;
        g_v2[n * KNB + lane] = myv2;
    }
}

// dinv from degree; restore g_deg/g_cnt to zero for the next replay.
__global__ void k_dinv() {
    int n = blockIdx.x * blockDim.x + threadIdx.x;
    if (n < NN) {
        float d = g_deg[n];
        g_dinv[n] = (d > 0.0f) ? rsqrtf(fmaxf(d, 1e-12f)) : 0.0f;
        g_deg[n] = 0.0f;
        g_cnt[n] = 0;
    }
}

// Assemble all four output segments with coalesced, write-only stores:
//   out[0..E)=dinv[i]*vs*dinv[j], out[E..2E)=dinv[i]*v2*dinv[j],
//   out[2E..3E)=vs, out[3E..4E)=v2.
__global__ void k_fin(const int* __restrict__ jj, float* __restrict__ out) {
    int e = blockIdx.x * blockDim.x + threadIdx.x;
    if (e >= EE) return;
    int i = e / KNB;
    float vs = g_vs[e], v2 = g_v2[e];
    float c = g_dinv[i] * __ldg(&g_dinv[__ldg(&jj[e])]);
    out[e]           = c * vs;
    out[EE + e]      = c * v2;
    out[2 * EE + e]  = vs;
    out[3 * EE + e]  = v2;
}

// ---------------- launcher ------------------------------------------------

extern "C" void kernel_launch(void* const* d_in, const int* in_sizes, int n_in,
                              void* d_out, int out_size) {
    const float* features = (const float*)d_in[0];
    const float* W1       = (const float*)d_in[1];
    const float* b1       = (const float*)d_in[2];
    const float* W2       = (const float*)d_in[3];
    const float* b2       = (const float*)d_in[4];
    const float* s_d      = (const float*)d_in[5];
    const int*   adj_row  = (const int*)d_in[6];
    const int*   adj_col  = (const int*)d_in[7];
    const int*   j_idx    = (const int*)d_in[9];
    float* out = (float*)d_out;

    const int BN = (NN + 255) / 256;
    const int BE = (EE + 255) / 256;
    const int BW = (32 * NN + 255) / 256;         // warp per node
    const int BG = NN / FD;                       // 625 gemm tiles

    // launch 1: gemm layer-1 + adjacency degree count (fused grid)
    k_gemm_count<<<BG + COUNT_BLOCKS, 256>>>(features, W1, g_xw, adj_col);
    k_scan<<<1, 1024>>>();                        // launch 2
    k_scatter<<<BE, 256>>>(adj_row, adj_col);     // launch 3

    // launch 4 (PROFILED): proven chunked gather, layer 1 — the last
    // never-cleanly-measured kernel in the pipeline.
    k_gather<<<BW, 256>>>(g_xw, g_h1, b1, 1);

    k_gemm<<<BG, 256>>>(g_h1, W2, g_xw, 1);       // launch 5
    k_gather<<<BW, 256>>>(g_xw, g_h2, b2, 2);     // launch 6 (layer 2 + norm)

    k_symscore<<<BW, 256>>>(g_h2, s_d, j_idx);    // launch 7 (fused pass)
    k_dinv<<<BN, 256>>>();                        // launch 8
    k_fin<<<BE, 256>>>(j_idx, out);               // launch 9

    (void)in_sizes; (void)n_in; (void)out_size;
}

// round 11
// speedup vs baseline: 1.3389x; 1.2362x over previous
#include <cuda_runtime.h>
#include <cuda_bf16.h>

// Problem constants (fixed shapes from reference setup_inputs)
#define NN 40000
#define FD 64
#define KNB 24
#define EE (NN * KNB)        // 960000 candidate edges (= E_ADJ too)
#define OMEGA_C 0.9f

// ---------------- scratch (device globals; no allocation allowed) ----------
__device__ float g_xw[NN * FD];    // X@W buffer (reused across layers)
__device__ float g_h1[NN * FD];    // layer-1 output
__device__ float g_h2[NN * FD];    // layer-2 normalized embedding
__device__ float g_dinva[NN];      // adjacency dinv (GCN symmetric norm)
__device__ int   g_cnt[NN];        // adjacency in-degree counts
__device__ int   g_off[NN + 1];    // CSR offsets (by dst col)
__device__ int   g_cur[NN];        // scatter cursors
__device__ int   g_src[EE];        // CSR payload: source row of each in-edge
__device__ float g_deg[NN];        // learner-graph degree
__device__ float g_dinv[NN];       // learner-graph dinv
__device__ float g_s[EE];          // per-edge blended score s_val

// ---------------- kernels -------------------------------------------------

__global__ void k_init() {
    int n = blockIdx.x * blockDim.x + threadIdx.x;
    if (n < NN) { g_cnt[n] = 0; g_deg[n] = 0.0f; }
}

__global__ void k_count(const int* __restrict__ col) {
    int e = blockIdx.x * blockDim.x + threadIdx.x;
    if (e < EE) atomicAdd(&g_cnt[col[e]], 1);
}

// Single-block exclusive scan of g_cnt -> g_off/g_cur; also computes dinva.
__global__ void k_scan() {
    __shared__ int wsum[32];
    int t = threadIdx.x;
    int lane = t & 31, w = t >> 5;
    int carry = 0;
    for (int base = 0; base < NN; base += 1024) {
        int i = base + t;
        int v = (i < NN) ? g_cnt[i] : 0;
        int x = v;
#pragma unroll
        for (int d = 1; d < 32; d <<= 1) {
            int y = __shfl_up_sync(0xffffffffu, x, d);
            if (lane >= d) x += y;
        }
        if (lane == 31) wsum[w] = x;
        __syncthreads();
        if (w == 0) {
            int s = wsum[lane];
#pragma unroll
            for (int d = 1; d < 32; d <<= 1) {
                int y = __shfl_up_sync(0xffffffffu, s, d);
                if (lane >= d) s += y;
            }
            wsum[lane] = s;
        }
        __syncthreads();
        int incl = x + (w > 0 ? wsum[w - 1] : 0);
        int excl = carry + incl - v;
        if (i < NN) {
            g_off[i] = excl;
            g_cur[i] = excl;
            g_dinva[i] = rsqrtf(1.0f + (float)v);
        }
        carry += wsum[31];
        __syncthreads();
    }
    if (t == 0) g_off[NN] = carry;
}

__global__ void k_scatter(const int* __restrict__ row, const int* __restrict__ col) {
    int e = blockIdx.x * blockDim.x + threadIdx.x;
    if (e >= EE) return;
    int c = col[e];
    int pos = atomicAdd(&g_cur[c], 1);
    g_src[pos] = row[e];
}

// xw[r][c] = X[r][:] @ W[:][c]  (64x64 tile / block; float4 global loads —
// the single measured-good change vs the round-4 baseline: 147us -> ~75us)
__global__ void k_gemm(const float* __restrict__ X, const float* __restrict__ W,
                       float* __restrict__ xw, int relu_in) {
    __shared__ float sW[FD * FD];        // [k][c]
    __shared__ float sX[FD * 68];        // padded stride
    int t = threadIdx.x;
    int rowBase = blockIdx.x * FD;
    const float4* W4 = (const float4*)W;
    const float4* X4 = (const float4*)(X + rowBase * FD);
#pragma unroll
    for (int i = 0; i < 4; i++) {
        int idx = t + i * 256;           // 0..1023 float4 index
        float4 w = W4[idx];
        ((float4*)sW)[idx] = w;
        float4 x = X4[idx];
        if (relu_in) {
            x.x = fmaxf(x.x, 0.0f); x.y = fmaxf(x.y, 0.0f);
            x.z = fmaxf(x.z, 0.0f); x.w = fmaxf(x.w, 0.0f);
        }
        int r = idx >> 4, c4 = idx & 15;
        *(float4*)&sX[r * 68 + c4 * 4] = x;
    }
    __syncthreads();

    int tx = t & 15, ty = t >> 4;
    int c0 = tx * 4, r0 = ty * 4;
    float acc[4][4];
#pragma unroll
    for (int r = 0; r < 4; r++)
#pragma unroll
        for (int c = 0; c < 4; c++) acc[r][c] = 0.0f;

#pragma unroll
    for (int k = 0; k < FD; k++) {
        float4 bw = *(const float4*)&sW[k * FD + c0];
        float a0 = sX[(r0 + 0) * 68 + k];
        float a1 = sX[(r0 + 1) * 68 + k];
        float a2 = sX[(r0 + 2) * 68 + k];
        float a3 = sX[(r0 + 3) * 68 + k];
        acc[0][0] += a0 * bw.x; acc[0][1] += a0 * bw.y; acc[0][2] += a0 * bw.z; acc[0][3] += a0 * bw.w;
        acc[1][0] += a1 * bw.x; acc[1][1] += a1 * bw.y; acc[1][2] += a1 * bw.z; acc[1][3] += a1 * bw.w;
        acc[2][0] += a2 * bw.x; acc[2][1] += a2 * bw.y; acc[2][2] += a2 * bw.z; acc[2][3] += a2 * bw.w;
        acc[3][0] += a3 * bw.x; acc[3][1] += a3 * bw.y; acc[3][2] += a3 * bw.z; acc[3][3] += a3 * bw.w;
    }

#pragma unroll
    for (int rr = 0; rr < 4; rr++) {
        int r = rowBase + r0 + rr;
        *(float4*)&xw[r * FD + c0] = make_float4(acc[rr][0], acc[rr][1],
                                                 acc[rr][2], acc[rr][3]);
    }
}

// Warp per dst node: out[c] = b + dinva[c]^2*xw[c] + sum_in coef*xw[r]
// Source indices + dinva pre-loaded coalesced in chunks of 32, then
// shfl-broadcast -> independent back-to-back row loads.
// mode 2: additionally L2-normalize the row (layer-2 epilogue fused).
__global__ void k_gather(const float* __restrict__ xw, float* __restrict__ out,
                         const float* __restrict__ b, int mode) {
    int tid = blockIdx.x * blockDim.x + threadIdx.x;
    int n = tid >> 5;
    if (n >= NN) return;
    int lane = tid & 31;
    float dc = g_dinva[n];
    float d2 = dc * dc;
    float2 a = ((const float2*)(xw + n * FD))[lane];
    float2 bb = ((const float2*)b)[lane];
    float2 acc = make_float2(bb.x + d2 * a.x, bb.y + d2 * a.y);
    int p0 = g_off[n], p1 = g_off[n + 1];
    for (int base = p0; base < p1; base += 32) {
        int cnt = min(32, p1 - base);
        int rsrc = 0;
        float din = 0.0f;
        if (base + lane < p1) {
            rsrc = __ldg(&g_src[base + lane]);
            din  = __ldg(&g_dinva[rsrc]);
        }
#pragma unroll 4
        for (int t = 0; t < cnt; t++) {
            int r = __shfl_sync(0xffffffffu, rsrc, t);
            float coef = dc * __shfl_sync(0xffffffffu, din, t);
            float2 v = ((const float2*)(xw + r * FD))[lane];
            acc.x += coef * v.x;
            acc.y += coef * v.y;
        }
    }
    if (mode == 2) {
        float s = acc.x * acc.x + acc.y * acc.y;
#pragma unroll
        for (int m = 16; m; m >>= 1) s += __shfl_xor_sync(0xffffffffu, s, m);
        float inv = 1.0f / fmaxf(sqrtf(s), 1e-12f);
        acc.x *= inv; acc.y *= inv;
    }
    ((float2*)(out + n * FD))[lane] = acc;
}

// Warp per node i: h[i] loaded once; 24 neighbor rows loaded coalesced.
__global__ void k_score(const float* __restrict__ h, const float* __restrict__ sd,
                        const int* __restrict__ jj) {
    int tid = blockIdx.x * blockDim.x + threadIdx.x;
    int n = tid >> 5;
    if (n >= NN) return;
    int lane = tid & 31;
    float2 hi = ((const float2*)(h + n * FD))[lane];
    int myj = 0; float mysd = 0.0f;
    if (lane < KNB) {
        myj  = __ldg(&jj[n * KNB + lane]);
        mysd = __ldg(&sd[n * KNB + lane]);
    }
    float mys = 0.0f;
#pragma unroll 4
    for (int t = 0; t < KNB; t++) {
        int j = __shfl_sync(0xffffffffu, myj, t);
        float2 hj = ((const float2*)(h + j * FD))[lane];
        float s = hi.x * hj.x + hi.y * hj.y;
#pragma unroll
        for (int m = 16; m; m >>= 1) s += __shfl_xor_sync(0xffffffffu, s, m);
        if (lane == t) mys = s;
    }
    if (lane < KNB)
        g_s[n * KNB + lane] = OMEGA_C * fmaxf(mys, 0.0f) + (1.0f - OMEGA_C) * mysd;
}

// Warp per node n. For each of its 24 edges (n, j_t): scan node j_t's
// candidate block COALESCED (lanes 0..23), ballot-match i==n, first set bit
// == reference's stable-argsort/searchsorted-left semantics. Writes vals_s
// halves into out[2E..4E); accumulates learner degrees (batched for n).
__global__ void k_sym(const int* __restrict__ jj, float* __restrict__ out) {
    int tid = blockIdx.x * blockDim.x + threadIdx.x;
    int n = tid >> 5;
    if (n >= NN) return;
    int lane = tid & 31;
    int myj = 0; float mys = 0.0f;
    if (lane < KNB) {
        myj = __ldg(&jj[n * KNB + lane]);
        mys = g_s[n * KNB + lane];
    }
    float myvs = 0.0f, myv2 = 0.0f, degn = 0.0f;
    for (int t = 0; t < KNB; t++) {
        int j = __shfl_sync(0xffffffffu, myj, t);
        float sv = __shfl_sync(0xffffffffu, mys, t);
        int cand = (lane < KNB) ? __ldg(&jj[j * KNB + lane]) : -1;
        unsigned m = __ballot_sync(0xffffffffu, cand == n);
        float vsym, v2;
        if (m) {                                   // uniform branch
            int idx = __ffs(m) - 1;
            float srev = g_s[j * KNB + idx];       // uniform broadcast load
            vsym = 0.5f * (sv + srev); v2 = 0.0f;
        } else {
            vsym = sv; v2 = sv;
            if (lane == 0) atomicAdd(&g_deg[j], vsym);
        }
        degn += vsym;
        if (lane == t) { myvs = vsym; myv2 = v2; }
    }
    if (lane == 0) atomicAdd(&g_deg[n], degn);
    if (lane < KNB) {
        out[2 * EE + n * KNB + lane] = myvs;
        out[3 * EE + n * KNB + lane] = myv2;
    }
}

__global__ void k_dinv() {
    int n = blockIdx.x * blockDim.x + threadIdx.x;
    if (n < NN) {
        float d = g_deg[n];
        g_dinv[n] = (d > 0.0f) ? rsqrtf(fmaxf(d, 1e-12f)) : 0.0f;
    }
}

// vals_norm = dinv[i]*vals_s*dinv[j]; i = e/24 (i_idx structure), coalesced.
__global__ void k_fin(const int* __restrict__ jj, float* __restrict__ out) {
    int e = blockIdx.x * blockDim.x + threadIdx.x;
    if (e >= EE) return;
    int i = e / KNB;
    float c = g_dinv[i] * __ldg(&g_dinv[jj[e]]);
    out[e]      = c * out[2 * EE + e];
    out[EE + e] = c * out[3 * EE + e];
}

// ---------------- launcher ------------------------------------------------

extern "C" void kernel_launch(void* const* d_in, const int* in_sizes, int n_in,
                              void* d_out, int out_size) {
    const float* features = (const float*)d_in[0];
    const float* W1       = (const float*)d_in[1];
    const float* b1       = (const float*)d_in[2];
    const float* W2       = (const float*)d_in[3];
    const float* b2       = (const float*)d_in[4];
    const float* s_d      = (const float*)d_in[5];
    const int*   adj_row  = (const int*)d_in[6];
    const int*   adj_col  = (const int*)d_in[7];
    const int*   j_idx    = (const int*)d_in[9];
    float* out = (float*)d_out;

    const int BN = (NN + 255) / 256;
    const int BE = (EE + 255) / 256;
    const int BW = (32 * NN + 255) / 256;     // warp per node
    const int BG = NN / FD;                   // 625 gemm tiles

    // CSR build (fixed adjacency; once per launch) — round-4 structure
    k_init<<<BN, 256>>>();
    k_count<<<BE, 256>>>(adj_col);
    k_scan<<<1, 1024>>>();
    k_scatter<<<BE, 256>>>(adj_row, adj_col);

    // GCN layer 1 (relu fused into next gemm's load)
    k_gemm<<<BG, 256>>>(features, W1, g_xw, 0);
    k_gather<<<BW, 256>>>(g_xw, g_h1, b1, 1);

    // GCN layer 2 + fused row L2-normalize
    k_gemm<<<BG, 256>>>(g_h1, W2, g_xw, 1);
    k_gather<<<BW, 256>>>(g_xw, g_h2, b2, 2);

    // edge scores (warp per node)
    k_score<<<BW, 256>>>(g_h2, s_d, j_idx);

    // symmetrize + degree + final normalization
    k_sym<<<BW, 256>>>(j_idx, out);
    k_dinv<<<BN, 256>>>();
    k_fin<<<BE, 256>>>(j_idx, out);

    (void)in_sizes; (void)n_in; (void)out_size;
}